// round 16
// baseline (speedup 1.0000x reference)
#include <cuda_runtime.h>

static constexpr int Bb = 128, Tt = 32, Dd = 128, Hh = 256, Oo = 128, Zz = 384;
static constexpr int GRID = 256;   // 16 h-groups x 16 b-groups
static constexpr int NT   = 512;   // 16 warps
static constexpr int HPC  = 16;    // h rows per CTA (1 per warp)
static constexpr int BPC  = 8;     // batches per CTA

// dynamic smem layout (floats)
static constexpr int PAR_F = HPC * 3 * Zz;   // 18432 : [h_local][W|lam|gam][384]
static constexpr int Z_F   = 2 * BPC * Zz;   // 6144  : z double buffer
static constexpr int HL_F  = HPC * BPC;      // 128   : h_T stash for epilogue
static constexpr int SMEM_BYTES = (PAR_F + Z_F + HL_F) * 4;  // 98816

__device__ volatile unsigned g_arrive[GRID];
__device__ volatile unsigned g_phase = 0;    // replay baseline only
__device__ float g_h[2][Bb * Hh];

__device__ __forceinline__ float tanh_fast(float x) {
    x = fminf(fmaxf(x, -8.f), 8.f);
    float e2 = __expf(2.f * x);
    return __fdividef(e2 - 1.f, e2 + 1.f);
}

__global__ __launch_bounds__(NT, 2)
void stpn_persistent_kernel(const float* __restrict__ sentence,  // [B,T,D]
                            const float* __restrict__ h0,        // [B,H]
                            const float* __restrict__ F0,        // [B,H,Z]
                            const float* __restrict__ Wm,        // [H,Z]
                            const float* __restrict__ bias,      // [H]
                            const float* __restrict__ lam,       // [H,Z]
                            const float* __restrict__ gam,       // [H,Z]
                            const float* __restrict__ Wout,      // [O,H]
                            const float* __restrict__ bout,      // [O]
                            float* __restrict__ out)
{
    float* out_tag = out;                       // [B,O]
    float* out_h   = out + Bb * Oo;             // [B,H]
    float* Fm      = out + Bb * Oo + Bb * Hh;   // [B,H,Z]

    extern __shared__ __align__(16) float smem[];
    float* s_par = smem;                 // params
    float* s_z   = smem + PAR_F;         // z buffers
    float* s_hl  = smem + PAR_F + Z_F;   // h_T stash
    __shared__ unsigned s_base;

    const int tid  = threadIdx.x;
    const int wid  = tid >> 5;
    const int lane = tid & 31;
    const int hg   = blockIdx.x >> 4;    // 0..15
    const int bg   = blockIdx.x & 15;    // 0..15
    const int h    = hg * HPC + wid;     // this warp's hidden index (global)
    const int b0   = bg * BPC;

    if (tid == 0) s_base = g_phase;      // per-replay phase baseline

    // ---- stage per-CTA parameter rows into smem (once) ----
    for (int idx = tid; idx < HPC * Zz; idx += NT) {
        int hl = idx / Zz, z = idx - hl * Zz;
        int g  = (hg * HPC + hl) * Zz + z;
        s_par[(hl * 3 + 0) * Zz + z] = Wm[g];
        s_par[(hl * 3 + 1) * Zz + z] = lam[g];
        s_par[(hl * 3 + 2) * Zz + z] = gam[g];
    }
    const float bias_h = bias[h];
    __syncthreads();
    const unsigned base = s_base;

    // Decentralized grid barrier: every CTA sweeps all flags itself.
    // One L2 hop (flag write -> flag reads) instead of three (flag -> leader
    // -> phase -> all). Flags are monotonic counters; wrap-safe compares.
    auto gridbar = [&](unsigned n) {
        const unsigned target = base + n;
        __syncthreads();
        if (tid == 0) { __threadfence(); g_arrive[blockIdx.x] = target; }
        if (wid == 0) {                      // warp 0 sweeps 8 flags/lane
            for (;;) {
                bool ok = true;
#pragma unroll
                for (int j = 0; j < 8; j++)
                    ok &= ((int)(g_arrive[lane * 8 + j] - target) >= 0);
                if (__all_sync(0xffffffffu, ok)) break;
                __nanosleep(128);
            }
            if (lane == 0) __threadfence();  // acquire: flags -> data
        }
        __syncthreads();
    };

    const float* pW = s_par + (wid * 3 + 0) * Zz;
    const float* pL = s_par + (wid * 3 + 1) * Zz;
    const float* pG = s_par + (wid * 3 + 2) * Zz;
    const size_t HZ = (size_t)Hh * Zz;

    for (int t = 1; t <= Tt; t++) {
        if (t > 1) gridbar((unsigned)(t - 1));   // h_{t-1} visible

        // ---- stage z_t = [x_t ; h_{t-1}] for this CTA's 8 batches ----
        float* buf = s_z + (t & 1) * (BPC * Zz);
        const float* hsrc = (t == 1) ? h0 : &g_h[(t - 1) & 1][0];
        for (int idx = tid; idx < BPC * Zz; idx += NT) {
            int bb = idx / Zz, z = idx - bb * Zz;
            int b  = b0 + bb;
            float v;
            if (z < Dd) v = sentence[((size_t)b * Tt + (t - 1)) * Dd + z];
            else        v = hsrc[b * Hh + (z - Dd)];
            buf[idx] = v;
        }
        __syncthreads();

        const float* zpb = s_z + ((t & 1) ^ 1) * (BPC * Zz);
        const bool first = (t == 1);
        const bool last  = (t == Tt);
        float* hdst = &g_h[t & 1][0];
        const float* Fbase = first ? F0 : Fm;

        size_t ro = ((size_t)b0 * Hh + h) * (size_t)Zz;
        for (int bb = 0; bb < BPC; bb++, ro += HZ) {
            int b = b0 + bb;
            const float* zt = buf + bb * Zz;
            const float* zp = zpb + bb * Zz;
            float hp = zt[Dd + h];   // h_{t-1}[b,h]

            float acc0 = 0.f, acc1 = 0.f;
#pragma unroll
            for (int i = 0; i < 3; i++) {
                int z = i * 128 + lane * 4;
                float4 Fv = *(const float4*)(Fbase + ro + z);
                float4 z4 = *(const float4*)(zt + z);
                float4 Wv = *(const float4*)(pW + z);
                float4 f;
                if (first) {
                    f = Fv;
                } else {
                    float4 lv  = *(const float4*)(pL + z);
                    float4 gv  = *(const float4*)(pG + z);
                    float4 zp4 = *(const float4*)(zp + z);
                    // f = lam*F_{t-2} + gam * h_{t-1}[b,h] * z_{t-1} = F_{t-1}
                    f.x = fmaf(lv.x, Fv.x, gv.x * (hp * zp4.x));
                    f.y = fmaf(lv.y, Fv.y, gv.y * (hp * zp4.y));
                    f.z = fmaf(lv.z, Fv.z, gv.z * (hp * zp4.z));
                    f.w = fmaf(lv.w, Fv.w, gv.w * (hp * zp4.w));
                }
                acc0 = fmaf(Wv.x + f.x, z4.x, acc0);
                acc1 = fmaf(Wv.y + f.y, z4.y, acc1);
                acc0 = fmaf(Wv.z + f.z, z4.z, acc0);
                acc1 = fmaf(Wv.w + f.w, z4.w, acc1);
                *(float4*)(Fm + ro + z) = f;    // memory <- F_{t-1}
            }
            float acc = acc0 + acc1;
#pragma unroll
            for (int off = 16; off > 0; off >>= 1)
                acc += __shfl_xor_sync(0xffffffffu, acc, off);
            float hn = tanh_fast(acc + bias_h);
            if (lane == 0) {
                hdst[b * Hh + h] = hn;
                if (last) {
                    out_h[b * Hh + h] = hn;
                    s_hl[wid * BPC + bb] = hn;
                }
            }
        }
    }

    // ---- epilogue: F_T = lam*F_{T-1} + gam * h_T (x) z_T  (CTA-local) ----
    __syncthreads();
    {
        const float* bufT = s_z + (Tt & 1) * (BPC * Zz);
        size_t ro = ((size_t)b0 * Hh + h) * (size_t)Zz;
        for (int bb = 0; bb < BPC; bb++, ro += HZ) {
            float hn = s_hl[wid * BPC + bb];
            const float* zt = bufT + bb * Zz;
#pragma unroll
            for (int i = 0; i < 3; i++) {
                int z = i * 128 + lane * 4;
                float4 f  = *(const float4*)(Fm + ro + z);
                float4 lv = *(const float4*)(pL + z);
                float4 gv = *(const float4*)(pG + z);
                float4 z4 = *(const float4*)(zt + z);
                float4 ft;
                ft.x = fmaf(lv.x, f.x, gv.x * (hn * z4.x));
                ft.y = fmaf(lv.y, f.y, gv.y * (hn * z4.y));
                ft.z = fmaf(lv.z, f.z, gv.z * (hn * z4.z));
                ft.w = fmaf(lv.w, f.w, gv.w * (hn * z4.w));
                *(float4*)(Fm + ro + z) = ft;
            }
        }
    }

    gridbar((unsigned)Tt);   // h_T + F_T visible everywhere

    // advance replay baseline (CTA 0 only, after everyone passed the last bar)
    if (blockIdx.x == 0 && tid == 0) g_phase = base + (unsigned)Tt;

    // ---- tag_space = h_T @ Wout^T + bout : 512 warps x 32 outputs ----
    if (blockIdx.x < 32) {
        const float* hT = &g_h[Tt & 1][0];
        int wglob = blockIdx.x * 16 + wid;    // 0..511
#pragma unroll
        for (int k = 0; k < 32; k++) {
            int oidx = wglob * 32 + k;        // 0..16383
            int b = oidx >> 7;
            int o = oidx & 127;
            float s = 0.f;
#pragma unroll
            for (int j = 0; j < 8; j++) {
                int hh = lane + 32 * j;
                s = fmaf(hT[b * Hh + hh], Wout[o * Hh + hh], s);
            }
#pragma unroll
            for (int off = 16; off > 0; off >>= 1)
                s += __shfl_xor_sync(0xffffffffu, s, off);
            if (lane == 0) out_tag[oidx] = s + bout[o];
        }
    }
}

extern "C" void kernel_launch(void* const* d_in, const int* in_sizes, int n_in,
                              void* d_out, int out_size)
{
    (void)in_sizes; (void)n_in; (void)out_size;
    const float* sentence = (const float*)d_in[0];
    const float* h0       = (const float*)d_in[1];
    const float* F0       = (const float*)d_in[2];
    const float* Wm       = (const float*)d_in[3];
    const float* bias     = (const float*)d_in[4];
    const float* lam      = (const float*)d_in[5];
    const float* gam      = (const float*)d_in[6];
    const float* Wout     = (const float*)d_in[7];
    const float* bout     = (const float*)d_in[8];
    float* out = (float*)d_out;

    // Unconditional (no static guards per harness contract); cheap + idempotent.
    cudaFuncSetAttribute(stpn_persistent_kernel,
                         cudaFuncAttributeMaxDynamicSharedMemorySize,
                         SMEM_BYTES);
    stpn_persistent_kernel<<<GRID, NT, SMEM_BYTES>>>(sentence, h0, F0, Wm, bias,
                                                     lam, gam, Wout, bout, out);
}